// round 1
// baseline (speedup 1.0000x reference)
#include <cuda_runtime.h>

#define BB 8
#define NN 4096
#define DD 1024
#define OUTD 1024
#define PASS_BLOCKS 64   // blocks per batch in the big pass (64 rows each)

// ---------------- device scratch (no allocations allowed) ----------------
__device__ __align__(16) float g_Wgm[DD * DD];
__device__ __align__(16) float g_WgmT[DD * DD];
__device__ __align__(16) float g_WfT[DD * DD];
__device__ __align__(16) float g_b[BB * NN];
__device__ __align__(16) float g_c[BB * NN];
__device__ __align__(16) float g_delta[BB * NN];
__device__ __align__(16) float g_q[BB * DD];
__device__ __align__(16) float g_qt[BB * DD];
__device__ __align__(16) float g_tmp[BB * DD];
__device__ __align__(16) float g_tmp2[BB * DD];
__device__ __align__(16) float g_outv[BB * DD];
__device__ __align__(16) float g_sbuf[BB * DD];
__device__ __align__(16) float g_part[BB * PASS_BLOCKS * DD];

// ---------------- small helpers ----------------
__device__ __forceinline__ float warpSum(float v) {
    #pragma unroll
    for (int o = 16; o; o >>= 1) v += __shfl_xor_sync(0xffffffffu, v, o);
    return v;
}
__device__ __forceinline__ float warpMax(float v) {
    #pragma unroll
    for (int o = 16; o; o >>= 1) v = fmaxf(v, __shfl_xor_sync(0xffffffffu, v, o));
    return v;
}

// ---------------- setup kernels ----------------
// Wgm = mean over g of W_g[g]  (1M elements, float4)
__global__ void __launch_bounds__(256) k_wgm(const float* __restrict__ Wg) {
    int i = blockIdx.x * 256 + threadIdx.x;       // < 262144 float4s
    const float4* W = (const float4*)Wg;
    float4 a = W[i], b = W[i + 262144], c = W[i + 524288], d = W[i + 786432];
    float4 r;
    r.x = 0.25f * (a.x + b.x + c.x + d.x);
    r.y = 0.25f * (a.y + b.y + c.y + d.y);
    r.z = 0.25f * (a.z + b.z + c.z + d.z);
    r.w = 0.25f * (a.w + b.w + c.w + d.w);
    ((float4*)g_Wgm)[i] = r;
}

// b logits init from mask (works for float32 or int32 masks: nonzero bits == True)
__global__ void __launch_bounds__(256) k_binit(const unsigned* __restrict__ mask) {
    int i = blockIdx.x * 256 + threadIdx.x;       // < 32768
    g_b[i] = (mask[i] != 0u) ? -1e18f : 0.0f;
}

// 1024x1024 transpose, tiled
__global__ void __launch_bounds__(256) k_transpose(float* __restrict__ dst,
                                                   const float* __restrict__ src) {
    __shared__ float tile[32][33];
    int x = blockIdx.x * 32 + threadIdx.x;
    int y0 = blockIdx.y * 32;
    #pragma unroll
    for (int r = threadIdx.y; r < 32; r += 8)
        tile[r][threadIdx.x] = src[(y0 + r) * DD + x];
    __syncthreads();
    int x2 = blockIdx.y * 32 + threadIdx.x;
    int y2 = blockIdx.x * 32;
    #pragma unroll
    for (int r = threadIdx.y; r < 32; r += 8)
        dst[(y2 + r) * DD + x2] = tile[threadIdx.x][r];
}

// q0[b,d] = sum_k query[b,k] * W_h[k,d]   (column-GEMV, coalesced over d)
__global__ void __launch_bounds__(256) k_q0(const float* __restrict__ query,
                                            const float* __restrict__ Wh) {
    __shared__ float sq[DD];
    int b = blockIdx.x >> 2;
    int d = ((blockIdx.x & 3) << 8) + threadIdx.x;
    for (int i = threadIdx.x; i < DD; i += 256) sq[i] = query[b * DD + i];
    __syncthreads();
    float a0 = 0, a1 = 0, a2 = 0, a3 = 0;
    #pragma unroll 4
    for (int k = 0; k < DD; k += 4) {
        a0 += sq[k + 0] * Wh[(k + 0) * DD + d];
        a1 += sq[k + 1] * Wh[(k + 1) * DD + d];
        a2 += sq[k + 2] * Wh[(k + 2) * DD + d];
        a3 += sq[k + 3] * Wh[(k + 3) * DD + d];
    }
    g_q[b * DD + d] = (a0 + a1) + (a2 + a3);
}

// ---------------- per-iteration small kernels ----------------
// c = softmax(b) per batch row (grid=8, 256 thr, 16 elems/thr)
__global__ void __launch_bounds__(256) k_softmax() {
    int b = blockIdx.x, t = threadIdx.x;
    __shared__ float red[8];
    float v[16];
    float mx = -3.0e38f;
    #pragma unroll
    for (int i = 0; i < 16; i++) { v[i] = g_b[b * NN + i * 256 + t]; mx = fmaxf(mx, v[i]); }
    mx = warpMax(mx);
    if ((t & 31) == 0) red[t >> 5] = mx;
    __syncthreads();
    mx = red[0];
    #pragma unroll
    for (int w = 1; w < 8; w++) mx = fmaxf(mx, red[w]);
    float sum = 0.f;
    #pragma unroll
    for (int i = 0; i < 16; i++) { v[i] = expf(v[i] - mx); sum += v[i]; }
    sum = warpSum(sum);
    __syncthreads();
    if ((t & 31) == 0) red[t >> 5] = sum;
    __syncthreads();
    sum = 0.f;
    #pragma unroll
    for (int w = 0; w < 8; w++) sum += red[w];
    float inv = 1.0f / sum;
    #pragma unroll
    for (int i = 0; i < 16; i++) g_c[b * NN + i * 256 + t] = v[i] * inv;
}

// Y[b,r] = dot(M[r,:], X[b,:])  for all 8 b.  grid=128 (8 warps x 16), 256 thr.
__global__ void __launch_bounds__(256) k_matvec8(const float* __restrict__ M,
                                                 const float* __restrict__ X,
                                                 float* __restrict__ Y) {
    __shared__ float shX[BB * DD];   // 32 KB
    const float4* Xv = (const float4*)X;
    float4* shXv = (float4*)shX;
    #pragma unroll
    for (int i = threadIdx.x; i < BB * DD / 4; i += 256) shXv[i] = Xv[i];
    __syncthreads();
    int warp = threadIdx.x >> 5, lane = threadIdx.x & 31;
    int r = blockIdx.x * 8 + warp;
    const float4* Mr = (const float4*)(M + (size_t)r * DD);
    float acc[BB];
    #pragma unroll
    for (int b = 0; b < BB; b++) acc[b] = 0.f;
    #pragma unroll
    for (int j = 0; j < 8; j++) {
        float4 m = Mr[j * 32 + lane];
        int base = (j * 32 + lane);
        #pragma unroll
        for (int b = 0; b < BB; b++) {
            float4 xv = shXv[b * (DD / 4) + base];
            acc[b] += m.x * xv.x + m.y * xv.y + m.z * xv.z + m.w * xv.w;
        }
    }
    #pragma unroll
    for (int b = 0; b < BB; b++) acc[b] = warpSum(acc[b]);
    if (lane == 0) {
        #pragma unroll
        for (int b = 0; b < BB; b++) Y[b * DD + r] = acc[b];
    }
}

// The big streaming pass over feat: delta[b,n] = feat[b,n,:].qt[b,:],
// partial s[b,:] = sum_n c[b,n]*feat[b,n,:].   grid=(PASS_BLOCKS, 8), 256 thr.
__global__ void __launch_bounds__(256) k_pass(const float* __restrict__ feat,
                                              int want_delta) {
    int b = blockIdx.y;
    int warp = threadIdx.x >> 5, lane = threadIdx.x & 31;
    __shared__ float4 sh_qt[DD / 4];
    __shared__ float4 sh_s[DD / 4];
    const float4* qtv = (const float4*)(g_qt + b * DD);
    for (int i = threadIdx.x; i < DD / 4; i += 256) sh_qt[i] = qtv[i];
    __syncthreads();

    const float4* fb = (const float4*)feat + (size_t)b * NN * (DD / 4);
    float4 sacc[8];
    #pragma unroll
    for (int j = 0; j < 8; j++) sacc[j] = make_float4(0.f, 0.f, 0.f, 0.f);

    int nbase = blockIdx.x * 64 + warp;
    #pragma unroll 2
    for (int k = 0; k < 8; k++) {
        int n = nbase + k * 8;
        const float4* rp = fb + (size_t)n * (DD / 4);
        float4 v[8];
        #pragma unroll
        for (int j = 0; j < 8; j++) v[j] = rp[j * 32 + lane];
        float cw = __ldg(&g_c[b * NN + n]);
        float dp0 = 0.f, dp1 = 0.f;
        #pragma unroll
        for (int j = 0; j < 8; j++) {
            float4 qv = sh_qt[j * 32 + lane];
            dp0 += v[j].x * qv.x + v[j].y * qv.y;
            dp1 += v[j].z * qv.z + v[j].w * qv.w;
            sacc[j].x += cw * v[j].x; sacc[j].y += cw * v[j].y;
            sacc[j].z += cw * v[j].z; sacc[j].w += cw * v[j].w;
        }
        float dp = warpSum(dp0 + dp1);
        if (want_delta && lane == 0) g_delta[b * NN + n] = dp;
    }

    // deterministic staggered block-reduce of the 8 warps' s accumulators
    #pragma unroll
    for (int w = 0; w < 8; w++) {
        if (warp == w) {
            #pragma unroll
            for (int j = 0; j < 8; j++) {
                int idx = j * 32 + lane;
                if (w == 0) sh_s[idx] = sacc[j];
                else {
                    float4 t = sh_s[idx];
                    t.x += sacc[j].x; t.y += sacc[j].y;
                    t.z += sacc[j].z; t.w += sacc[j].w;
                    sh_s[idx] = t;
                }
            }
        }
        __syncthreads();
    }
    float4* pp = (float4*)(g_part + ((size_t)b * PASS_BLOCKS + blockIdx.x) * DD);
    for (int i = threadIdx.x; i < DD / 4; i += 256) pp[i] = sh_s[i];
}

// reduce per-block partials -> g_sbuf   (grid=32, 256 thr)
__global__ void __launch_bounds__(256) k_sreduce() {
    int i = blockIdx.x * 256 + threadIdx.x;   // < 8192
    int b = i >> 10, d = i & 1023;
    float acc = 0.f;
    #pragma unroll 8
    for (int k = 0; k < PASS_BLOCKS; k++)
        acc += g_part[((size_t)b * PASS_BLOCKS + k) * DD + d];
    g_sbuf[i] = acc;
}

// standardize delta (ddof=1) and b += delta_norm  (grid=8, 256 thr)
__global__ void __launch_bounds__(256) k_bupdate() {
    int b = blockIdx.x, t = threadIdx.x;
    __shared__ float red[16];
    float v[16];
    float s1 = 0.f, s2 = 0.f;
    #pragma unroll
    for (int i = 0; i < 16; i++) {
        v[i] = g_delta[b * NN + i * 256 + t];
        s1 += v[i]; s2 += v[i] * v[i];
    }
    s1 = warpSum(s1); s2 = warpSum(s2);
    if ((t & 31) == 0) { red[t >> 5] = s1; red[8 + (t >> 5)] = s2; }
    __syncthreads();
    s1 = 0.f; s2 = 0.f;
    #pragma unroll
    for (int w = 0; w < 8; w++) { s1 += red[w]; s2 += red[8 + w]; }
    float mean = s1 / (float)NN;
    float var = fmaxf((s2 - s1 * s1 / (float)NN) / (float)(NN - 1), 0.f);
    float inv = 1.0f / (sqrtf(var) + 1e-9f);
    #pragma unroll
    for (int i = 0; i < 16; i++)
        g_b[b * NN + i * 256 + t] += (v[i] - mean) * inv;
}

// q = LayerNorm(q + selu(outv*invn))  (grid=8, 256 thr, 4 elems/thr)
__global__ void __launch_bounds__(256) k_qupdate(const float* __restrict__ lnw,
                                                 const float* __restrict__ lnb,
                                                 float invn) {
    const float SELU_A = 1.6732632423543772f;
    const float SELU_S = 1.0507009873554805f;
    int b = blockIdx.x, t = threadIdx.x;
    __shared__ float red[16];
    float v[4];
    float s1 = 0.f, s2 = 0.f;
    #pragma unroll
    for (int i = 0; i < 4; i++) {
        int d = i * 256 + t;
        float x = g_outv[b * DD + d] * invn;
        float se = (x > 0.f) ? SELU_S * x : SELU_S * SELU_A * expm1f(x);
        v[i] = g_q[b * DD + d] + se;
        s1 += v[i]; s2 += v[i] * v[i];
    }
    s1 = warpSum(s1); s2 = warpSum(s2);
    if ((t & 31) == 0) { red[t >> 5] = s1; red[8 + (t >> 5)] = s2; }
    __syncthreads();
    s1 = 0.f; s2 = 0.f;
    #pragma unroll
    for (int w = 0; w < 8; w++) { s1 += red[w]; s2 += red[8 + w]; }
    float mu = s1 / (float)DD;
    float var = fmaxf(s2 / (float)DD - mu * mu, 0.f);
    float rstd = rsqrtf(var + 1e-5f);
    #pragma unroll
    for (int i = 0; i < 4; i++) {
        int d = i * 256 + t;
        g_q[b * DD + d] = (v[i] - mu) * rstd * lnw[d] + lnb[d];
    }
}

// final: out[b,o] = dot(W_out[o,:], q[b,:]) + b_out[o]   (grid=128, 256 thr)
__global__ void __launch_bounds__(256) k_final(const float* __restrict__ Wout,
                                               const float* __restrict__ bout,
                                               float* __restrict__ out) {
    __shared__ float shX[BB * DD];
    const float4* Xv = (const float4*)g_q;
    float4* shXv = (float4*)shX;
    #pragma unroll
    for (int i = threadIdx.x; i < BB * DD / 4; i += 256) shXv[i] = Xv[i];
    __syncthreads();
    int warp = threadIdx.x >> 5, lane = threadIdx.x & 31;
    int r = blockIdx.x * 8 + warp;
    const float4* Mr = (const float4*)(Wout + (size_t)r * DD);
    float acc[BB];
    #pragma unroll
    for (int b = 0; b < BB; b++) acc[b] = 0.f;
    #pragma unroll
    for (int j = 0; j < 8; j++) {
        float4 m = Mr[j * 32 + lane];
        int base = j * 32 + lane;
        #pragma unroll
        for (int b = 0; b < BB; b++) {
            float4 xv = shXv[b * (DD / 4) + base];
            acc[b] += m.x * xv.x + m.y * xv.y + m.z * xv.z + m.w * xv.w;
        }
    }
    #pragma unroll
    for (int b = 0; b < BB; b++) acc[b] = warpSum(acc[b]);
    if (lane == 0) {
        float bo = bout[r];
        #pragma unroll
        for (int b = 0; b < BB; b++) out[b * OUTD + r] = acc[b] + bo;
    }
}

// ---------------- host orchestration ----------------
extern "C" void kernel_launch(void* const* d_in, const int* in_sizes, int n_in,
                              void* d_out, int out_size) {
    const float* query = (const float*)d_in[0];
    const float* feat  = (const float*)d_in[1];
    const float* W_h   = (const float*)d_in[2];
    const float* W_f   = (const float*)d_in[3];
    const float* W_g   = (const float*)d_in[4];
    const float* ln_w  = (const float*)d_in[5];
    const float* ln_b  = (const float*)d_in[6];
    const float* W_out = (const float*)d_in[7];
    const float* b_out = (const float*)d_in[8];
    const unsigned* mask = (const unsigned*)d_in[9];
    float* out = (float*)d_out;

    float *pWgm, *pWgmT, *pWfT, *pQ, *pQt, *pTmp, *pTmp2, *pOutv, *pS;
    cudaGetSymbolAddress((void**)&pWgm,  g_Wgm);
    cudaGetSymbolAddress((void**)&pWgmT, g_WgmT);
    cudaGetSymbolAddress((void**)&pWfT,  g_WfT);
    cudaGetSymbolAddress((void**)&pQ,    g_q);
    cudaGetSymbolAddress((void**)&pQt,   g_qt);
    cudaGetSymbolAddress((void**)&pTmp,  g_tmp);
    cudaGetSymbolAddress((void**)&pTmp2, g_tmp2);
    cudaGetSymbolAddress((void**)&pOutv, g_outv);
    cudaGetSymbolAddress((void**)&pS,    g_sbuf);

    // setup
    k_wgm<<<1024, 256>>>(W_g);
    k_binit<<<128, 256>>>(mask);
    k_transpose<<<dim3(32, 32), dim3(32, 8)>>>(pWgmT, pWgm);
    k_transpose<<<dim3(32, 32), dim3(32, 8)>>>(pWfT, W_f);
    k_q0<<<32, 256>>>(query, W_h);

    for (int it = 0; it < 3; it++) {
        bool last = (it == 2);
        k_softmax<<<8, 256>>>();
        if (!last) {
            k_matvec8<<<128, 256>>>(pWgmT, pQ, pTmp);   // tmp = Wgm^T q
            k_matvec8<<<128, 256>>>(W_f, pTmp, pQt);    // qt = W_f tmp
        }
        k_pass<<<dim3(PASS_BLOCKS, BB), 256>>>(feat, last ? 0 : 1);
        k_sreduce<<<32, 256>>>();
        if (!last) k_bupdate<<<8, 256>>>();
        k_matvec8<<<128, 256>>>(pWfT, pS, pTmp2);       // tmp2 = W_f^T s
        k_matvec8<<<128, 256>>>(pWgm, pTmp2, pOutv);    // outv = Wgm tmp2
        k_qupdate<<<8, 256>>>(ln_w, ln_b, last ? 1.0f : (1.0f / (float)NN));
    }
    k_final<<<128, 256>>>(W_out, b_out, out);
}